// round 1
// baseline (speedup 1.0000x reference)
#include <cuda_runtime.h>
#include <cstdint>

// Problem constants: S=16, P=8, N=64, D=128
#define NBLK   128          // S*P independent blocks
#define NROW   64           // N
#define DIMD   128          // D
#define STRIDE 130          // smem row stride in floats (bank-conflict-free for LDS.64 pattern)

// ---- packed f32x2 helpers (sm_103a) ----
__device__ __forceinline__ void fma2(unsigned long long& d, unsigned long long a,
                                     unsigned long long b, unsigned long long c) {
    asm("fma.rn.f32x2 %0, %1, %2, %3;" : "=l"(d) : "l"(a), "l"(b), "l"(c));
}
__device__ __forceinline__ unsigned long long add2(unsigned long long a, unsigned long long b) {
    unsigned long long d;
    asm("add.rn.f32x2 %0, %1, %2;" : "=l"(d) : "l"(a), "l"(b));
    return d;
}
__device__ __forceinline__ float lo32(unsigned long long v) {
    return __uint_as_float((unsigned)(v & 0xffffffffULL));
}
__device__ __forceinline__ float hi32(unsigned long long v) {
    return __uint_as_float((unsigned)(v >> 32));
}

// Dynamic smem layout:
//   sx   : [64][STRIDE] floats   (x block)
//   sy   : [64][STRIDE] floats   (NEGATED y block)
//   nx2[64], rnx[64], ny2[64], rny[64]
#define SMEM_FLOATS (2 * NROW * STRIDE + 4 * NROW)

__global__ void __launch_bounds__(256, 1)
vcmp_kernel(const float* __restrict__ X, const float* __restrict__ Y,
            float* __restrict__ out) {
    extern __shared__ float smem[];
    float* sx  = smem;
    float* sy  = smem + NROW * STRIDE;
    float* nx2 = sy + NROW * STRIDE;
    float* rnx = nx2 + NROW;
    float* ny2 = rnx + NROW;
    float* rny = ny2 + NROW;

    const int blk = blockIdx.x;
    const int t   = threadIdx.x;

    // ---- Load x and -y into padded smem (coalesced float4 global loads) ----
    const float4* xg = (const float4*)(X + (size_t)blk * NROW * DIMD);
    const float4* yg = (const float4*)(Y + (size_t)blk * NROW * DIMD);
#pragma unroll
    for (int k = 0; k < 8; k++) {
        int g    = k * 256 + t;     // float4 index, 0..2047
        int row  = g >> 5;          // 32 float4 per row
        int col4 = (g & 31) * 4;
        float4 xv = xg[g];
        float4 yv = yg[g];
        float* dx = sx + row * STRIDE + col4;
        dx[0] = xv.x; dx[1] = xv.y; dx[2] = xv.z; dx[3] = xv.w;
        float* dy = sy + row * STRIDE + col4;
        dy[0] = -yv.x; dy[1] = -yv.y; dy[2] = -yv.z; dy[3] = -yv.w;
    }
    __syncthreads();

    // ---- Per-row squared norms + reciprocal norms (128 threads, 1 row each) ----
    if (t < 128) {
        const float* r = (t < NROW) ? (sx + t * STRIDE) : (sy + (t - NROW) * STRIDE);
        float ss = 0.f;
#pragma unroll 8
        for (int d = 0; d < DIMD; d++) ss = fmaf(r[d], r[d], ss);
        float rn = 1.0f / fmaxf(sqrtf(ss), 1e-12f);
        if (t < NROW) { nx2[t] = ss; rnx[t] = rn; }
        else          { ny2[t - NROW] = ss; rny[t - NROW] = rn; }
    }
    __syncthreads();

    // ---- Main loop: 4x4 pair tile per thread, packed f32x2 over d ----
    const int ng = t >> 4;   // 0..15 -> n = ng*4 + i
    const int mg = t & 15;   //        -> m = mg + 16*j  (conflict-free y LDS)
    const float* xp = sx + (ng * 4) * STRIDE;
    const float* yp = sy + mg * STRIDE;

    unsigned long long ndot[4][4];  // accumulates x*(-y) packed -> -dot
    unsigned long long l1a[4][4];   // accumulates |x-y| packed
#pragma unroll
    for (int i = 0; i < 4; i++)
#pragma unroll
        for (int j = 0; j < 4; j++) { ndot[i][j] = 0ULL; l1a[i][j] = 0ULL; }

    const unsigned long long ABSMASK = 0x7fffffff7fffffffULL;

#pragma unroll 4
    for (int d = 0; d < DIMD; d += 2) {
        unsigned long long xv[4], yv[4];
#pragma unroll
        for (int i = 0; i < 4; i++)
            xv[i] = *(const unsigned long long*)(xp + i * STRIDE + d);
#pragma unroll
        for (int j = 0; j < 4; j++)
            yv[j] = *(const unsigned long long*)(yp + j * 16 * STRIDE + d);

#pragma unroll
        for (int i = 0; i < 4; i++) {
#pragma unroll
            for (int j = 0; j < 4; j++) {
                unsigned long long diff = add2(xv[i], yv[j]);       // x + (-y)
                fma2(ndot[i][j], xv[i], yv[j], ndot[i][j]);         // -= x*y
                l1a[i][j] = add2(l1a[i][j], diff & ABSMASK);        // += |x-y|
            }
        }
    }

    // ---- Epilogue: cos / l2 / l1 per pair ----
    float* oblk = out + (size_t)blk * NROW * NROW * 3;
#pragma unroll
    for (int i = 0; i < 4; i++) {
        const int n   = ng * 4 + i;
        const float xn2 = nx2[n];
        const float rxn = rnx[n];
#pragma unroll
        for (int j = 0; j < 4; j++) {
            const int m = mg + 16 * j;
            unsigned long long nd = ndot[i][j];
            float dotv = -(lo32(nd) + hi32(nd));
            unsigned long long la = l1a[i][j];
            float l1v = lo32(la) + hi32(la);
            float arg = fmaxf(xn2 + ny2[m] - 2.0f * dotv, 0.0f);
            float l2v = sqrtf(arg);
            float cosv = dotv * rxn * rny[m];
            float* o = oblk + (size_t)(n * NROW + m) * 3;
            o[0] = cosv; o[1] = l2v; o[2] = l1v;
        }
    }
}

extern "C" void kernel_launch(void* const* d_in, const int* in_sizes, int n_in,
                              void* d_out, int out_size) {
    const float* X = (const float*)d_in[0];
    const float* Y = (const float*)d_in[1];
    float* out = (float*)d_out;

    const int smem_bytes = SMEM_FLOATS * (int)sizeof(float);   // 67,584 B
    cudaFuncSetAttribute(vcmp_kernel, cudaFuncAttributeMaxDynamicSharedMemorySize,
                         smem_bytes);
    vcmp_kernel<<<NBLK, 256, smem_bytes>>>(X, Y, out);
}

// round 2
// speedup vs baseline: 1.0168x; 1.0168x over previous
#include <cuda_runtime.h>
#include <cstdint>

// Problem constants: S=16, P=8, N=64, D=128
#define NBLK   128          // S*P independent blocks
#define NROW   64           // N
#define DIMD   128          // D
#define STRIDE 130          // smem row stride in floats (bank-conflict-free)
#define NTHR   512

// ---- packed f32x2 helpers (sm_103a) ----
__device__ __forceinline__ void fma2(unsigned long long& d, unsigned long long a,
                                     unsigned long long b, unsigned long long c) {
    asm("fma.rn.f32x2 %0, %1, %2, %3;" : "=l"(d) : "l"(a), "l"(b), "l"(c));
}
__device__ __forceinline__ unsigned long long add2(unsigned long long a, unsigned long long b) {
    unsigned long long d;
    asm("add.rn.f32x2 %0, %1, %2;" : "=l"(d) : "l"(a), "l"(b));
    return d;
}
__device__ __forceinline__ float lo32(unsigned long long v) {
    return __uint_as_float((unsigned)(v & 0xffffffffULL));
}
__device__ __forceinline__ float hi32(unsigned long long v) {
    return __uint_as_float((unsigned)(v >> 32));
}

// Dynamic smem layout:
//   sx   : [64][STRIDE] floats   (x block)
//   sy   : [64][STRIDE] floats   (NEGATED y block)
//   nx2[64], rnx[64], ny2[64], rny[64]
#define SMEM_FLOATS (2 * NROW * STRIDE + 4 * NROW)

__global__ void __launch_bounds__(NTHR, 1)
vcmp_kernel(const float* __restrict__ X, const float* __restrict__ Y,
            float* __restrict__ out) {
    extern __shared__ float smem[];
    float* sx  = smem;
    float* sy  = smem + NROW * STRIDE;
    float* nx2 = sy + NROW * STRIDE;
    float* rnx = nx2 + NROW;
    float* ny2 = rnx + NROW;
    float* rny = ny2 + NROW;

    const int blk = blockIdx.x;
    const int t   = threadIdx.x;

    // ---- Load x and -y into padded smem (coalesced float4 global loads) ----
    const float4* xg = (const float4*)(X + (size_t)blk * NROW * DIMD);
    const float4* yg = (const float4*)(Y + (size_t)blk * NROW * DIMD);
#pragma unroll
    for (int k = 0; k < 4; k++) {
        int g    = k * NTHR + t;    // float4 index, 0..2047
        int row  = g >> 5;          // 32 float4 per row
        int col4 = (g & 31) * 4;
        float4 xv = xg[g];
        float4 yv = yg[g];
        float* dx = sx + row * STRIDE + col4;
        dx[0] = xv.x; dx[1] = xv.y; dx[2] = xv.z; dx[3] = xv.w;
        float* dy = sy + row * STRIDE + col4;
        dy[0] = -yv.x; dy[1] = -yv.y; dy[2] = -yv.z; dy[3] = -yv.w;
    }
    __syncthreads();

    // ---- Per-row squared norms + reciprocal norms (128 threads, 1 row each) ----
    if (t < 128) {
        const float* r = (t < NROW) ? (sx + t * STRIDE) : (sy + (t - NROW) * STRIDE);
        float ss = 0.f;
#pragma unroll 8
        for (int d = 0; d < DIMD; d++) ss = fmaf(r[d], r[d], ss);
        float rn = 1.0f / fmaxf(sqrtf(ss), 1e-12f);
        if (t < NROW) { nx2[t] = ss; rnx[t] = rn; }
        else          { ny2[t - NROW] = ss; rny[t - NROW] = rn; }
    }
    __syncthreads();

    // ---- Main loop: 2x4 pair tile per thread, packed f32x2 over d ----
    // n = ng*2 + i (ng = t>>4, 0..31), m = mg + 16*j (mg = t&15)
    const int ng = t >> 4;
    const int mg = t & 15;
    const float* xp = sx + (ng * 2) * STRIDE;
    const float* yp = sy + mg * STRIDE;

    unsigned long long ndot[2][4];  // accumulates x*(-y) packed -> -dot
    unsigned long long l1a[2][4];   // accumulates |x-y| packed
#pragma unroll
    for (int i = 0; i < 2; i++)
#pragma unroll
        for (int j = 0; j < 4; j++) { ndot[i][j] = 0ULL; l1a[i][j] = 0ULL; }

    const unsigned long long ABSMASK = 0x7fffffff7fffffffULL;

#pragma unroll 4
    for (int d = 0; d < DIMD; d += 2) {
        unsigned long long xv[2], yv[4];
#pragma unroll
        for (int i = 0; i < 2; i++)
            xv[i] = *(const unsigned long long*)(xp + i * STRIDE + d);
#pragma unroll
        for (int j = 0; j < 4; j++)
            yv[j] = *(const unsigned long long*)(yp + j * 16 * STRIDE + d);

#pragma unroll
        for (int i = 0; i < 2; i++) {
#pragma unroll
            for (int j = 0; j < 4; j++) {
                unsigned long long diff = add2(xv[i], yv[j]);       // x + (-y)
                fma2(ndot[i][j], xv[i], yv[j], ndot[i][j]);         // -= x*y
                l1a[i][j] = add2(l1a[i][j], diff & ABSMASK);        // += |x-y|
            }
        }
    }

    // ---- Epilogue: cos / l2 / l1 per pair ----
    float* oblk = out + (size_t)blk * NROW * NROW * 3;
#pragma unroll
    for (int i = 0; i < 2; i++) {
        const int n     = ng * 2 + i;
        const float xn2 = nx2[n];
        const float rxn = rnx[n];
#pragma unroll
        for (int j = 0; j < 4; j++) {
            const int m = mg + 16 * j;
            unsigned long long nd = ndot[i][j];
            float dotv = -(lo32(nd) + hi32(nd));
            unsigned long long la = l1a[i][j];
            float l1v = lo32(la) + hi32(la);
            float arg = fmaxf(xn2 + ny2[m] - 2.0f * dotv, 0.0f);
            float l2v = sqrtf(arg);
            float cosv = dotv * rxn * rny[m];
            float* o = oblk + (size_t)(n * NROW + m) * 3;
            o[0] = cosv; o[1] = l2v; o[2] = l1v;
        }
    }
}

extern "C" void kernel_launch(void* const* d_in, const int* in_sizes, int n_in,
                              void* d_out, int out_size) {
    const float* X = (const float*)d_in[0];
    const float* Y = (const float*)d_in[1];
    float* out = (float*)d_out;

    const int smem_bytes = SMEM_FLOATS * (int)sizeof(float);   // 67,584 B
    cudaFuncSetAttribute(vcmp_kernel, cudaFuncAttributeMaxDynamicSharedMemorySize,
                         smem_bytes);
    vcmp_kernel<<<NBLK, NTHR, smem_bytes>>>(X, Y, out);
}

// round 3
// speedup vs baseline: 1.0303x; 1.0133x over previous
#include <cuda_runtime.h>
#include <cstdint>

// Problem constants: S=16, P=8, N=64, D=128
#define NBLK   128          // S*P independent blocks
#define NROW   64           // N
#define DIMD   128          // D
#define STRIDE 132          // smem row floats: conflict-free LDS.128 + pad-safe prefetch
#define NTHR   512

// ---- packed f32x2 helpers (sm_103a) ----
__device__ __forceinline__ void fma2(unsigned long long& d, unsigned long long a,
                                     unsigned long long b, unsigned long long c) {
    asm("fma.rn.f32x2 %0, %1, %2, %3;" : "=l"(d) : "l"(a), "l"(b), "l"(c));
}
__device__ __forceinline__ unsigned long long add2(unsigned long long a, unsigned long long b) {
    unsigned long long d;
    asm("add.rn.f32x2 %0, %1, %2;" : "=l"(d) : "l"(a), "l"(b));
    return d;
}
__device__ __forceinline__ float lo32(unsigned long long v) {
    return __uint_as_float((unsigned)(v & 0xffffffffULL));
}
__device__ __forceinline__ float hi32(unsigned long long v) {
    return __uint_as_float((unsigned)(v >> 32));
}

// smem: sx[64][STRIDE], sy[64][STRIDE] (negated y), nx2/rnx/ny2/rny[64]
#define SMEM_FLOATS (2 * NROW * STRIDE + 4 * NROW)

#define ABSMASK 0x7fffffff7fffffffULL

// One pipeline stage: 8 pairs x one d-quad (two f32x2 halves each)
#define STEP(BX, BY)                                                          \
    _Pragma("unroll")                                                         \
    for (int i = 0; i < 2; i++) {                                             \
        _Pragma("unroll")                                                     \
        for (int j = 0; j < 4; j++) {                                         \
            unsigned long long d0 = add2(BX[i].x, BY[j].x);                   \
            unsigned long long d1 = add2(BX[i].y, BY[j].y);                   \
            fma2(ndot[i][j], BX[i].x, BY[j].x, ndot[i][j]);                   \
            fma2(ndot[i][j], BX[i].y, BY[j].y, ndot[i][j]);                   \
            l1a[i][j] = add2(l1a[i][j], d0 & ABSMASK);                        \
            l1a[i][j] = add2(l1a[i][j], d1 & ABSMASK);                        \
        }                                                                     \
    }

__global__ void __launch_bounds__(NTHR, 1)
vcmp_kernel(const float* __restrict__ X, const float* __restrict__ Y,
            float* __restrict__ out) {
    extern __shared__ float smem[];
    float* sx  = smem;
    float* sy  = smem + NROW * STRIDE;
    float* nx2 = sy + NROW * STRIDE;
    float* rnx = nx2 + NROW;
    float* ny2 = rnx + NROW;
    float* rny = ny2 + NROW;

    const int blk = blockIdx.x;
    const int t   = threadIdx.x;

    // ---- Load x and -y into padded smem (coalesced float4 global loads) ----
    const float4* xg = (const float4*)(X + (size_t)blk * NROW * DIMD);
    const float4* yg = (const float4*)(Y + (size_t)blk * NROW * DIMD);
#pragma unroll
    for (int k = 0; k < 4; k++) {
        int g    = k * NTHR + t;    // float4 index, 0..2047
        int row  = g >> 5;          // 32 float4 per row
        int col4 = (g & 31) * 4;
        float4 xv = xg[g];
        float4 yv = yg[g];
        float4* dx = (float4*)(sx + row * STRIDE + col4);
        *dx = xv;
        float4* dy = (float4*)(sy + row * STRIDE + col4);
        *dy = make_float4(-yv.x, -yv.y, -yv.z, -yv.w);
    }
    __syncthreads();

    // ---- Per-row squared norms + reciprocal norms ----
    if (t < 128) {
        const float* r = (t < NROW) ? (sx + t * STRIDE) : (sy + (t - NROW) * STRIDE);
        float ss = 0.f;
#pragma unroll 8
        for (int d = 0; d < DIMD; d++) ss = fmaf(r[d], r[d], ss);
        float rn = 1.0f / fmaxf(sqrtf(ss), 1e-12f);
        if (t < NROW) { nx2[t] = ss; rnx[t] = rn; }
        else          { ny2[t - NROW] = ss; rny[t - NROW] = rn; }
    }
    __syncthreads();

    // ---- Main loop: 2x4 pair tile, LDS.128, 2-stage software pipeline ----
    const int ng = t >> 4;   // 0..31 -> n = ng*2 + i
    const int mg = t & 15;   //        -> m = mg + 16*j
    const float* xp0 = sx + (ng * 2) * STRIDE;
    const float* yp0 = sy + mg * STRIDE;

    unsigned long long ndot[2][4];  // accumulates x*(-y) -> -dot
    unsigned long long l1a[2][4];   // accumulates |x-y|
#pragma unroll
    for (int i = 0; i < 2; i++)
#pragma unroll
        for (int j = 0; j < 4; j++) { ndot[i][j] = 0ULL; l1a[i][j] = 0ULL; }

    ulonglong2 ax[2], ay[4], bx[2], by[4];

    // prime stage A at d = 0
#pragma unroll
    for (int i = 0; i < 2; i++)
        ax[i] = *(const ulonglong2*)(xp0 + i * STRIDE);
#pragma unroll
    for (int j = 0; j < 4; j++)
        ay[j] = *(const ulonglong2*)(yp0 + j * 16 * STRIDE);

#pragma unroll 2
    for (int d = 0; d < DIMD; d += 8) {
        // prefetch stage B at d+4
#pragma unroll
        for (int i = 0; i < 2; i++)
            bx[i] = *(const ulonglong2*)(xp0 + i * STRIDE + d + 4);
#pragma unroll
        for (int j = 0; j < 4; j++)
            by[j] = *(const ulonglong2*)(yp0 + j * 16 * STRIDE + d + 4);

        STEP(ax, ay)

        // prefetch stage A at d+8 (d=120 -> reads row padding cols 128..131: in-bounds, unused)
#pragma unroll
        for (int i = 0; i < 2; i++)
            ax[i] = *(const ulonglong2*)(xp0 + i * STRIDE + d + 8);
#pragma unroll
        for (int j = 0; j < 4; j++)
            ay[j] = *(const ulonglong2*)(yp0 + j * 16 * STRIDE + d + 8);

        STEP(bx, by)
    }

    // ---- Epilogue: cos / l2 / l1 per pair ----
    float* oblk = out + (size_t)blk * NROW * NROW * 3;
#pragma unroll
    for (int i = 0; i < 2; i++) {
        const int n     = ng * 2 + i;
        const float xn2 = nx2[n];
        const float rxn = rnx[n];
#pragma unroll
        for (int j = 0; j < 4; j++) {
            const int m = mg + 16 * j;
            unsigned long long nd = ndot[i][j];
            float dotv = -(lo32(nd) + hi32(nd));
            unsigned long long la = l1a[i][j];
            float l1v = lo32(la) + hi32(la);
            float arg = fmaxf(xn2 + ny2[m] - 2.0f * dotv, 0.0f);
            float l2v = sqrtf(arg);
            float cosv = dotv * rxn * rny[m];
            float* o = oblk + (size_t)(n * NROW + m) * 3;
            o[0] = cosv; o[1] = l2v; o[2] = l1v;
        }
    }
}

extern "C" void kernel_launch(void* const* d_in, const int* in_sizes, int n_in,
                              void* d_out, int out_size) {
    const float* X = (const float*)d_in[0];
    const float* Y = (const float*)d_in[1];
    float* out = (float*)d_out;

    const int smem_bytes = SMEM_FLOATS * (int)sizeof(float);   // 68,608 B
    cudaFuncSetAttribute(vcmp_kernel, cudaFuncAttributeMaxDynamicSharedMemorySize,
                         smem_bytes);
    vcmp_kernel<<<NBLK, NTHR, smem_bytes>>>(X, Y, out);
}

// round 4
// speedup vs baseline: 1.0342x; 1.0038x over previous
#include <cuda_runtime.h>
#include <cstdint>

// Problem constants: S=16, P=8, N=64, D=128
#define NBLK   128          // S*P independent blocks
#define NROW   64           // N
#define DIMD   128          // D
#define STRIDE 132          // conflict-free LDS.128 at 32-lane groups + pad-safe prefetch
#define NTHR   1024

// ---- packed f32x2 helpers (sm_103a) ----
__device__ __forceinline__ void fma2(unsigned long long& d, unsigned long long a,
                                     unsigned long long b, unsigned long long c) {
    asm("fma.rn.f32x2 %0, %1, %2, %3;" : "=l"(d) : "l"(a), "l"(b), "l"(c));
}
__device__ __forceinline__ unsigned long long add2(unsigned long long a, unsigned long long b) {
    unsigned long long d;
    asm("add.rn.f32x2 %0, %1, %2;" : "=l"(d) : "l"(a), "l"(b));
    return d;
}
__device__ __forceinline__ float lo32(unsigned long long v) {
    return __uint_as_float((unsigned)(v & 0xffffffffULL));
}
__device__ __forceinline__ float hi32(unsigned long long v) {
    return __uint_as_float((unsigned)(v >> 32));
}

// smem: sx[64][STRIDE], sy[64][STRIDE] (negated y), nx2/rnx/ny2/rny[64]
#define SMEM_FLOATS (2 * NROW * STRIDE + 4 * NROW)

#define ABSMASK 0x7fffffff7fffffffULL

// One pipeline stage: 4 pairs x one d-quad (two f32x2 halves each)
#define STEP(BX, BY)                                                          \
    _Pragma("unroll")                                                         \
    for (int i = 0; i < 2; i++) {                                             \
        _Pragma("unroll")                                                     \
        for (int j = 0; j < 2; j++) {                                         \
            unsigned long long d0 = add2(BX[i].x, BY[j].x);                   \
            unsigned long long d1 = add2(BX[i].y, BY[j].y);                   \
            fma2(ndot[i][j], BX[i].x, BY[j].x, ndot[i][j]);                   \
            fma2(ndot[i][j], BX[i].y, BY[j].y, ndot[i][j]);                   \
            l1a[i][j] = add2(l1a[i][j], d0 & ABSMASK);                        \
            l1a[i][j] = add2(l1a[i][j], d1 & ABSMASK);                        \
        }                                                                     \
    }

__global__ void __launch_bounds__(NTHR, 1)
vcmp_kernel(const float* __restrict__ X, const float* __restrict__ Y,
            float* __restrict__ out) {
    extern __shared__ float smem[];
    float* sx  = smem;
    float* sy  = smem + NROW * STRIDE;
    float* nx2 = sy + NROW * STRIDE;
    float* rnx = nx2 + NROW;
    float* ny2 = rnx + NROW;
    float* rny = ny2 + NROW;

    const int blk = blockIdx.x;
    const int t   = threadIdx.x;

    // ---- Load x and -y into padded smem (coalesced float4 global loads) ----
    const float4* xg = (const float4*)(X + (size_t)blk * NROW * DIMD);
    const float4* yg = (const float4*)(Y + (size_t)blk * NROW * DIMD);
#pragma unroll
    for (int k = 0; k < 2; k++) {
        int g    = k * NTHR + t;    // float4 index, 0..2047
        int row  = g >> 5;          // 32 float4 per row
        int col4 = (g & 31) * 4;
        float4 xv = xg[g];
        float4 yv = yg[g];
        *(float4*)(sx + row * STRIDE + col4) = xv;
        *(float4*)(sy + row * STRIDE + col4) = make_float4(-yv.x, -yv.y, -yv.z, -yv.w);
    }
    __syncthreads();

    // ---- Per-row squared norms + reciprocal norms (128 threads, 1 row each) ----
    if (t < 128) {
        const float* r = (t < NROW) ? (sx + t * STRIDE) : (sy + (t - NROW) * STRIDE);
        float ss = 0.f;
#pragma unroll 8
        for (int d = 0; d < DIMD; d++) ss = fmaf(r[d], r[d], ss);
        float rn = 1.0f / fmaxf(sqrtf(ss), 1e-12f);
        if (t < NROW) { nx2[t] = ss; rnx[t] = rn; }
        else          { ny2[t - NROW] = ss; rny[t - NROW] = rn; }
    }
    __syncthreads();

    // ---- Main loop: 2x2 pair tile per thread, LDS.128, 2-stage pipeline ----
    // n = ng*2 + i (ng = t>>5, 0..31)   -> x LDS is a warp-wide broadcast
    // m = mg + 32*j (mg = t&31)         -> y LDS conflict-free (STRIDE%32==4)
    const int ng = t >> 5;
    const int mg = t & 31;
    const float* xp0 = sx + (ng * 2) * STRIDE;
    const float* yp0 = sy + mg * STRIDE;

    unsigned long long ndot[2][2];  // accumulates x*(-y) -> -dot
    unsigned long long l1a[2][2];   // accumulates |x-y|
#pragma unroll
    for (int i = 0; i < 2; i++)
#pragma unroll
        for (int j = 0; j < 2; j++) { ndot[i][j] = 0ULL; l1a[i][j] = 0ULL; }

    ulonglong2 ax[2], ay[2], bx[2], by[2];

    // prime stage A at d = 0
#pragma unroll
    for (int i = 0; i < 2; i++)
        ax[i] = *(const ulonglong2*)(xp0 + i * STRIDE);
#pragma unroll
    for (int j = 0; j < 2; j++)
        ay[j] = *(const ulonglong2*)(yp0 + j * 32 * STRIDE);

#pragma unroll 2
    for (int d = 0; d < DIMD; d += 8) {
        // prefetch stage B at d+4
#pragma unroll
        for (int i = 0; i < 2; i++)
            bx[i] = *(const ulonglong2*)(xp0 + i * STRIDE + d + 4);
#pragma unroll
        for (int j = 0; j < 2; j++)
            by[j] = *(const ulonglong2*)(yp0 + j * 32 * STRIDE + d + 4);

        STEP(ax, ay)

        // prefetch stage A at d+8 (d=120 reads pad cols 128..131: in-bounds, unused)
#pragma unroll
        for (int i = 0; i < 2; i++)
            ax[i] = *(const ulonglong2*)(xp0 + i * STRIDE + d + 8);
#pragma unroll
        for (int j = 0; j < 2; j++)
            ay[j] = *(const ulonglong2*)(yp0 + j * 32 * STRIDE + d + 8);

        STEP(bx, by)
    }

    // ---- Epilogue: cos / l2 / l1 per pair ----
    float* oblk = out + (size_t)blk * NROW * NROW * 3;
#pragma unroll
    for (int i = 0; i < 2; i++) {
        const int n     = ng * 2 + i;
        const float xn2 = nx2[n];
        const float rxn = rnx[n];
#pragma unroll
        for (int j = 0; j < 2; j++) {
            const int m = mg + 32 * j;
            unsigned long long nd = ndot[i][j];
            float dotv = -(lo32(nd) + hi32(nd));
            unsigned long long la = l1a[i][j];
            float l1v = lo32(la) + hi32(la);
            float arg = fmaxf(xn2 + ny2[m] - 2.0f * dotv, 0.0f);
            float l2v = sqrtf(arg);
            float cosv = dotv * rxn * rny[m];
            float* o = oblk + (size_t)(n * NROW + m) * 3;
            o[0] = cosv; o[1] = l2v; o[2] = l1v;
        }
    }
}

extern "C" void kernel_launch(void* const* d_in, const int* in_sizes, int n_in,
                              void* d_out, int out_size) {
    const float* X = (const float*)d_in[0];
    const float* Y = (const float*)d_in[1];
    float* out = (float*)d_out;

    const int smem_bytes = SMEM_FLOATS * (int)sizeof(float);   // 68,608 B
    cudaFuncSetAttribute(vcmp_kernel, cudaFuncAttributeMaxDynamicSharedMemorySize,
                         smem_bytes);
    vcmp_kernel<<<NBLK, NTHR, smem_bytes>>>(X, Y, out);
}